// round 6
// baseline (speedup 1.0000x reference)
#include <cuda_runtime.h>
#include <cuda_fp16.h>

// Problem constants
#define BB 4
#define LL 1024
#define CC 1280
#define HH 20
#define DH 64
#define BHH (BB*HH)        // 80
#define BANK 40
#define LPOOL 256          // (32/2)*(32/2)
#define LKV (LL + LPOOL)   // 1280
#define ALPHA_C 0.48f      // 0.8 * 0.6
#define QSCALE 0.125f      // 1/sqrt(64)

// Scratch (device globals are allowed; cudaMalloc is not)
__device__ float g_q[BB*LL*CC];
__device__ float g_k[BB*LL*CC];
__device__ float g_v[BB*LL*CC];
__device__ float g_ctx[BB*LL*CC];
__device__ float g_Kb[BANK*LPOOL*DH];
__device__ float g_Vb[BANK*LPOOL*DH];

__device__ __forceinline__ float fp16_round(float x) {
    return __half2float(__float2half_rn(x));
}

// ---------------------------------------------------------------------------
// Bank KV preprocessing: fp16 round -> 2x2 avg pool over 32x32 grid -> *ALPHA
// ---------------------------------------------------------------------------
__global__ void pool_kernel(const float* __restrict__ Kg,
                            const float* __restrict__ Vg) {
    int idx = blockIdx.x * blockDim.x + threadIdx.x;
    const int total = BANK * LPOOL * DH;
    if (idx >= total) return;
    int d  = idx % DH;
    int p  = (idx / DH) % LPOOL;
    int bh = idx / (DH * LPOOL);
    int ph = p >> 4;          // /16
    int pw = p & 15;
    int t0 = (2 * ph) * 32 + 2 * pw;
    long base = ((long)bh * LL + t0) * DH + d;

    float ks = fp16_round(Kg[base])         + fp16_round(Kg[base + DH])
             + fp16_round(Kg[base + 32*DH]) + fp16_round(Kg[base + 33*DH]);
    float vs = fp16_round(Vg[base])         + fp16_round(Vg[base + DH])
             + fp16_round(Vg[base + 32*DH]) + fp16_round(Vg[base + 33*DH]);
    g_Kb[idx] = ALPHA_C * (ks * 0.25f);
    g_Vb[idx] = ALPHA_C * (vs * 0.25f);
}

// ---------------------------------------------------------------------------
// SGEMM: Cout[M,N] = A[M,K] @ W[K,N] (+ bias). 128x128 tile, BK=8, 8x8/thread
// ---------------------------------------------------------------------------
__global__ __launch_bounds__(256)
void sgemm_kernel(const float* __restrict__ A, const float* __restrict__ W,
                  const float* __restrict__ bias, float* __restrict__ Cout,
                  int M, int N, int K) {
    __shared__ float As[8][128];   // transposed A tile
    __shared__ float Bs[8][128];

    int tid = threadIdx.x;
    int tx = tid & 15;
    int ty = tid >> 4;
    int m0 = blockIdx.y * 128;
    int n0 = blockIdx.x * 128;

    float acc[8][8];
#pragma unroll
    for (int i = 0; i < 8; i++)
#pragma unroll
        for (int j = 0; j < 8; j++) acc[i][j] = 0.f;

    for (int k0 = 0; k0 < K; k0 += 8) {
        {
            int i = tid * 4;            // 0..1020
            int row = i >> 3;
            int kc = i & 7;             // 0 or 4
            float4 a = *(const float4*)(A + (long)(m0 + row) * K + k0 + kc);
            As[kc + 0][row] = a.x;
            As[kc + 1][row] = a.y;
            As[kc + 2][row] = a.z;
            As[kc + 3][row] = a.w;
            int kr = i >> 7;
            int col = i & 127;
            *(float4*)(&Bs[kr][col]) =
                *(const float4*)(W + (long)(k0 + kr) * N + n0 + col);
        }
        __syncthreads();

#pragma unroll
        for (int kk = 0; kk < 8; kk++) {
            float a[8], b[8];
            *(float4*)(a)     = *(float4*)(&As[kk][ty * 8]);
            *(float4*)(a + 4) = *(float4*)(&As[kk][ty * 8 + 4]);
            *(float4*)(b)     = *(float4*)(&Bs[kk][tx * 8]);
            *(float4*)(b + 4) = *(float4*)(&Bs[kk][tx * 8 + 4]);
#pragma unroll
            for (int i = 0; i < 8; i++)
#pragma unroll
                for (int j = 0; j < 8; j++)
                    acc[i][j] = fmaf(a[i], b[j], acc[i][j]);
        }
        __syncthreads();
    }

    float bv[8];
#pragma unroll
    for (int j = 0; j < 8; j++)
        bv[j] = bias ? bias[n0 + tx * 8 + j] : 0.f;

#pragma unroll
    for (int i = 0; i < 8; i++) {
        long row = m0 + ty * 8 + i;
        float4 o0, o1;
        o0.x = acc[i][0] + bv[0]; o0.y = acc[i][1] + bv[1];
        o0.z = acc[i][2] + bv[2]; o0.w = acc[i][3] + bv[3];
        o1.x = acc[i][4] + bv[4]; o1.y = acc[i][5] + bv[5];
        o1.z = acc[i][6] + bv[6]; o1.w = acc[i][7] + bv[7];
        *(float4*)(Cout + row * N + n0 + tx * 8)     = o0;
        *(float4*)(Cout + row * N + n0 + tx * 8 + 4) = o1;
    }
}

// ---------------------------------------------------------------------------
// Flash attention: per block = (one head, 64 q rows), kv len = 1280
// Static smem 48KB exactly: QsT[64][64], KsP[64][64] (K^T, reused for P), Vs[64][64]
// ---------------------------------------------------------------------------
__global__ __launch_bounds__(256)
void flash_kernel(const float* __restrict__ q, const float* __restrict__ k,
                  const float* __restrict__ v, float* __restrict__ ctx) {
    __shared__ float QsT[64 * 64];   // d-major
    __shared__ float KsP[64 * 64];   // d-major K^T; reused as P [q][kv]
    __shared__ float Vs[64 * 64];    // row-major

    int tid = threadIdx.x;
    int tx = tid & 15;
    int ty = tid >> 4;
    int bh = blockIdx.y;
    int bb = bh / HH;
    int hh = bh % HH;
    int q0 = blockIdx.x * 64;

    const float* qbase = q + ((long)bb * LL + q0) * CC + hh * DH;

    // Load Q tile transposed + pre-scale
#pragma unroll
    for (int i = 0; i < 4; i++) {
        int idx = tid + i * 256;      // 0..1023
        int row = idx >> 4;
        int dv  = (idx & 15) * 4;
        float4 val = *(const float4*)(qbase + (long)row * CC + dv);
        QsT[(dv + 0) * 64 + row] = val.x * QSCALE;
        QsT[(dv + 1) * 64 + row] = val.y * QSCALE;
        QsT[(dv + 2) * 64 + row] = val.z * QSCALE;
        QsT[(dv + 3) * 64 + row] = val.w * QSCALE;
    }

    float m_i[4], l_i[4], o[4][4];
#pragma unroll
    for (int i = 0; i < 4; i++) {
        m_i[i] = -1e30f;
        l_i[i] = 0.f;
#pragma unroll
        for (int j = 0; j < 4; j++) o[i][j] = 0.f;
    }

    for (int kt = 0; kt < LKV / 64; kt++) {
        int j0 = kt * 64;
        const float *kb, *vb;
        long stride;
        if (j0 < LL) {
            kb = k + ((long)bb * LL + j0) * CC + hh * DH;
            vb = v + ((long)bb * LL + j0) * CC + hh * DH;
            stride = CC;
        } else {
            long off = ((long)(bh % BANK) * LPOOL + (j0 - LL)) * DH;
            kb = g_Kb + off;
            vb = g_Vb + off;
            stride = DH;
        }

        __syncthreads();   // prior iter done reading KsP(P)/Vs; QsT ready (kt==0)
#pragma unroll
        for (int i = 0; i < 4; i++) {
            int idx = tid + i * 256;
            int row = idx >> 4;
            int dv  = (idx & 15) * 4;
            float4 kv4 = *(const float4*)(kb + (long)row * stride + dv);
            KsP[(dv + 0) * 64 + row] = kv4.x;
            KsP[(dv + 1) * 64 + row] = kv4.y;
            KsP[(dv + 2) * 64 + row] = kv4.z;
            KsP[(dv + 3) * 64 + row] = kv4.w;
            float4 vv4 = *(const float4*)(vb + (long)row * stride + dv);
            *(float4*)(&Vs[row * 64 + dv]) = vv4;
        }
        __syncthreads();

        // S = Q K^T  (64x64 tile; 4x4 per thread)
        float s[4][4];
#pragma unroll
        for (int i = 0; i < 4; i++)
#pragma unroll
            for (int j = 0; j < 4; j++) s[i][j] = 0.f;

#pragma unroll 16
        for (int d = 0; d < 64; d++) {
            float4 a = *(float4*)(&QsT[d * 64 + ty * 4]);
            float4 b = *(float4*)(&KsP[d * 64 + tx * 4]);
            float av[4] = {a.x, a.y, a.z, a.w};
            float bw[4] = {b.x, b.y, b.z, b.w};
#pragma unroll
            for (int i = 0; i < 4; i++)
#pragma unroll
                for (int j = 0; j < 4; j++)
                    s[i][j] = fmaf(av[i], bw[j], s[i][j]);
        }

        __syncthreads();   // everyone done reading K^T before P overwrites it

        // Online softmax update; write P into KsP as [q][kv] (q-major)
#pragma unroll
        for (int i = 0; i < 4; i++) {
            float mx = fmaxf(fmaxf(s[i][0], s[i][1]), fmaxf(s[i][2], s[i][3]));
#pragma unroll
            for (int w = 1; w < 16; w <<= 1)
                mx = fmaxf(mx, __shfl_xor_sync(0xffffffffu, mx, w));
            float mnew = fmaxf(m_i[i], mx);
            float sc = __expf(m_i[i] - mnew);
            m_i[i] = mnew;

            float su = 0.f;
#pragma unroll
            for (int j = 0; j < 4; j++) {
                float p = __expf(s[i][j] - mnew);
                su += p;
                KsP[(ty * 4 + i) * 64 + tx * 4 + j] = p;
            }
#pragma unroll
            for (int w = 1; w < 16; w <<= 1)
                su += __shfl_xor_sync(0xffffffffu, su, w);
            l_i[i] = l_i[i] * sc + su;
#pragma unroll
            for (int j = 0; j < 4; j++) o[i][j] *= sc;
        }
        __syncthreads();

        // O += P @ V
#pragma unroll 16
        for (int c = 0; c < 64; c++) {
            float p0 = KsP[(ty * 4 + 0) * 64 + c];
            float p1 = KsP[(ty * 4 + 1) * 64 + c];
            float p2 = KsP[(ty * 4 + 2) * 64 + c];
            float p3 = KsP[(ty * 4 + 3) * 64 + c];
            float4 vv = *(float4*)(&Vs[c * 64 + tx * 4]);
            float vw[4] = {vv.x, vv.y, vv.z, vv.w};
#pragma unroll
            for (int j = 0; j < 4; j++) {
                o[0][j] = fmaf(p0, vw[j], o[0][j]);
                o[1][j] = fmaf(p1, vw[j], o[1][j]);
                o[2][j] = fmaf(p2, vw[j], o[2][j]);
                o[3][j] = fmaf(p3, vw[j], o[3][j]);
            }
        }
    }

    // Normalize + write ctx in [B, L, H*Dh] layout
#pragma unroll
    for (int i = 0; i < 4; i++) {
        float inv = 1.f / l_i[i];
        int row = q0 + ty * 4 + i;
        float4 outv;
        outv.x = o[i][0] * inv;
        outv.y = o[i][1] * inv;
        outv.z = o[i][2] * inv;
        outv.w = o[i][3] * inv;
        *(float4*)(&ctx[((long)bb * LL + row) * CC + hh * DH + tx * 4]) = outv;
    }
}

// ---------------------------------------------------------------------------
extern "C" void kernel_launch(void* const* d_in, const int* in_sizes, int n_in,
                              void* d_out, int out_size) {
    const float* hs  = (const float*)d_in[0];
    const float* Wq  = (const float*)d_in[1];
    const float* Wk  = (const float*)d_in[2];
    const float* Wv  = (const float*)d_in[3];
    const float* Wo  = (const float*)d_in[4];
    const float* bo  = (const float*)d_in[5];
    const float* Kbg = (const float*)d_in[6];
    const float* Vbg = (const float*)d_in[7];
    float* out = (float*)d_out;

    float *gq, *gk, *gv, *gctx;
    cudaGetSymbolAddress((void**)&gq,   g_q);
    cudaGetSymbolAddress((void**)&gk,   g_k);
    cudaGetSymbolAddress((void**)&gv,   g_v);
    cudaGetSymbolAddress((void**)&gctx, g_ctx);

    // 1. Bank KV pool
    {
        int total = BANK * LPOOL * DH;
        pool_kernel<<<(total + 255) / 256, 256>>>(Kbg, Vbg);
    }

    // 2. QKV projections
    {
        dim3 grid(CC / 128, (BB * LL) / 128);   // (10, 32)
        sgemm_kernel<<<grid, 256>>>(hs, Wq, nullptr, gq, BB * LL, CC, CC);
        sgemm_kernel<<<grid, 256>>>(hs, Wk, nullptr, gk, BB * LL, CC, CC);
        sgemm_kernel<<<grid, 256>>>(hs, Wv, nullptr, gv, BB * LL, CC, CC);
    }

    // 3. Flash attention (static 48KB smem — no attribute opt-in needed)
    {
        dim3 grid(LL / 64, BHH);   // (16, 80)
        flash_kernel<<<grid, 256>>>(gq, gk, gv, gctx);
    }

    // 4. Output projection + bias
    {
        dim3 grid(CC / 128, (BB * LL) / 128);
        sgemm_kernel<<<grid, 256>>>(gctx, Wo, bo, out, BB * LL, CC, CC);
    }
}

// round 7
// speedup vs baseline: 1.5204x; 1.5204x over previous
#include <cuda_runtime.h>
#include <cuda_fp16.h>

// Problem constants
#define BB 4
#define LL 1024
#define CC 1280
#define HH 20
#define DH 64
#define BHH (BB*HH)        // 80
#define BANK 40
#define LPOOL 256          // (32/2)*(32/2)
#define LKV (LL + LPOOL)   // 1280
#define ALPHA_C 0.48f      // 0.8 * 0.6
#define QSCALE 0.125f      // 1/sqrt(64)

// Scratch (device globals are allowed; cudaMalloc is not)
__device__ float g_q[BB*LL*CC];
__device__ float g_k[BB*LL*CC];
__device__ float g_v[BB*LL*CC];
__device__ float g_ctx[BB*LL*CC];
__device__ float g_Kb[BANK*LPOOL*DH];
__device__ float g_Vb[BANK*LPOOL*DH];

__device__ __forceinline__ float fp16_round(float x) {
    return __half2float(__float2half_rn(x));
}

__device__ __forceinline__ unsigned f2tf32(float x) {
    unsigned r;
    asm("cvt.rna.tf32.f32 %0, %1;" : "=r"(r) : "f"(x));
    return r;
}

// d += a(16x8 tf32, row) * b(8x8 tf32, col)
__device__ __forceinline__ void mma_tf32(float* d, const unsigned* a, const unsigned* b) {
    asm volatile(
        "mma.sync.aligned.m16n8k8.row.col.f32.tf32.tf32.f32 "
        "{%0,%1,%2,%3}, {%4,%5,%6,%7}, {%8,%9}, {%0,%1,%2,%3};\n"
        : "+f"(d[0]), "+f"(d[1]), "+f"(d[2]), "+f"(d[3])
        : "r"(a[0]), "r"(a[1]), "r"(a[2]), "r"(a[3]),
          "r"(b[0]), "r"(b[1]));
}

// ---------------------------------------------------------------------------
// Bank KV preprocessing: fp16 round -> 2x2 avg pool over 32x32 grid -> *ALPHA
// ---------------------------------------------------------------------------
__global__ void pool_kernel(const float* __restrict__ Kg,
                            const float* __restrict__ Vg) {
    int idx = blockIdx.x * blockDim.x + threadIdx.x;
    const int total = BANK * LPOOL * DH;
    if (idx >= total) return;
    int d  = idx % DH;
    int p  = (idx / DH) % LPOOL;
    int bh = idx / (DH * LPOOL);
    int ph = p >> 4;          // /16
    int pw = p & 15;
    int t0 = (2 * ph) * 32 + 2 * pw;
    long base = ((long)bh * LL + t0) * DH + d;

    float ks = fp16_round(Kg[base])         + fp16_round(Kg[base + DH])
             + fp16_round(Kg[base + 32*DH]) + fp16_round(Kg[base + 33*DH]);
    float vs = fp16_round(Vg[base])         + fp16_round(Vg[base + DH])
             + fp16_round(Vg[base + 32*DH]) + fp16_round(Vg[base + 33*DH]);
    g_Kb[idx] = ALPHA_C * (ks * 0.25f);
    g_Vb[idx] = ALPHA_C * (vs * 0.25f);
}

// ---------------------------------------------------------------------------
// tf32 tensor-core GEMM: C[M,N] = A[M,K] @ W[K,N] (+bias)
// Block 128x128x32, 256 threads = 8 warps (2m x 4n), warp tile 64x32.
// Smem padded: As stride 36, Bs stride 132 -> conflict-free fragment loads.
// ---------------------------------------------------------------------------
#define BKT 32
#define ASTR 36
#define BSTR 132

__global__ __launch_bounds__(256)
void tgemm_kernel(const float* __restrict__ A, const float* __restrict__ W,
                  const float* __restrict__ bias, float* __restrict__ C,
                  int M, int N, int K) {
    __shared__ unsigned As[128 * ASTR];   // [m][k] tf32 bits
    __shared__ unsigned Bs[BKT * BSTR];   // [k][n] tf32 bits

    int tid  = threadIdx.x;
    int lane = tid & 31;
    int wid  = tid >> 5;
    int wm   = wid >> 2;          // 0..1  (64 rows each)
    int wn   = wid & 3;           // 0..3  (32 cols each)
    int g    = lane >> 2;         // 0..7
    int tg   = lane & 3;          // 0..3
    int m0 = blockIdx.y * 128;
    int n0 = blockIdx.x * 128;

    float acc[4][4][4];
#pragma unroll
    for (int i = 0; i < 4; i++)
#pragma unroll
        for (int j = 0; j < 4; j++)
#pragma unroll
            for (int r = 0; r < 4; r++) acc[i][j][r] = 0.f;

    int arow  = tid >> 1;             // 0..127
    int akseg = (tid & 1) * 16;       // 0 or 16
    int brow  = tid >> 3;             // 0..31
    int bnseg = (tid & 7) * 16;       // 0..112

    for (int k0 = 0; k0 < K; k0 += BKT) {
        const float* ap = A + (long)(m0 + arow) * K + k0 + akseg;
        const float* bp = W + (long)(k0 + brow) * N + n0 + bnseg;
#pragma unroll
        for (int i = 0; i < 4; i++) {
            float4 av = *(const float4*)(ap + 4 * i);
            unsigned* ad = &As[arow * ASTR + akseg + 4 * i];
            ad[0] = f2tf32(av.x); ad[1] = f2tf32(av.y);
            ad[2] = f2tf32(av.z); ad[3] = f2tf32(av.w);
            float4 bv = *(const float4*)(bp + 4 * i);
            unsigned* bd = &Bs[brow * BSTR + bnseg + 4 * i];
            bd[0] = f2tf32(bv.x); bd[1] = f2tf32(bv.y);
            bd[2] = f2tf32(bv.z); bd[3] = f2tf32(bv.w);
        }
        __syncthreads();

#pragma unroll
        for (int kk = 0; kk < BKT; kk += 8) {
            unsigned af[4][4], bf[4][2];
#pragma unroll
            for (int mf = 0; mf < 4; mf++) {
                int r = wm * 64 + mf * 16;
                af[mf][0] = As[(r + g    ) * ASTR + kk + tg    ];
                af[mf][1] = As[(r + g + 8) * ASTR + kk + tg    ];
                af[mf][2] = As[(r + g    ) * ASTR + kk + tg + 4];
                af[mf][3] = As[(r + g + 8) * ASTR + kk + tg + 4];
            }
#pragma unroll
            for (int nf = 0; nf < 4; nf++) {
                int c = wn * 32 + nf * 8 + g;
                bf[nf][0] = Bs[(kk + tg    ) * BSTR + c];
                bf[nf][1] = Bs[(kk + tg + 4) * BSTR + c];
            }
#pragma unroll
            for (int mf = 0; mf < 4; mf++)
#pragma unroll
                for (int nf = 0; nf < 4; nf++)
                    mma_tf32(acc[mf][nf], af[mf], bf[nf]);
        }
        __syncthreads();
    }

    // Epilogue
#pragma unroll
    for (int mf = 0; mf < 4; mf++) {
        long r0 = m0 + wm * 64 + mf * 16 + g;
#pragma unroll
        for (int nf = 0; nf < 4; nf++) {
            int c = n0 + wn * 32 + nf * 8 + tg * 2;
            float b0 = bias ? bias[c] : 0.f;
            float b1 = bias ? bias[c + 1] : 0.f;
            float2 v0 = {acc[mf][nf][0] + b0, acc[mf][nf][1] + b1};
            float2 v1 = {acc[mf][nf][2] + b0, acc[mf][nf][3] + b1};
            *(float2*)(C + r0 * N + c)       = v0;
            *(float2*)(C + (r0 + 8) * N + c) = v1;
        }
    }
}

// ---------------------------------------------------------------------------
// Flash attention: per block = (one head, 64 q rows), kv len = 1280
// Static smem 48KB exactly: QsT[64][64], KsP[64][64] (K^T, reused for P), Vs[64][64]
// ---------------------------------------------------------------------------
__global__ __launch_bounds__(256)
void flash_kernel(const float* __restrict__ q, const float* __restrict__ k,
                  const float* __restrict__ v, float* __restrict__ ctx) {
    __shared__ float QsT[64 * 64];   // d-major
    __shared__ float KsP[64 * 64];   // d-major K^T; reused as P [q][kv]
    __shared__ float Vs[64 * 64];    // row-major

    int tid = threadIdx.x;
    int tx = tid & 15;
    int ty = tid >> 4;
    int bh = blockIdx.y;
    int bb = bh / HH;
    int hh = bh % HH;
    int q0 = blockIdx.x * 64;

    const float* qbase = q + ((long)bb * LL + q0) * CC + hh * DH;

#pragma unroll
    for (int i = 0; i < 4; i++) {
        int idx = tid + i * 256;
        int row = idx >> 4;
        int dv  = (idx & 15) * 4;
        float4 val = *(const float4*)(qbase + (long)row * CC + dv);
        QsT[(dv + 0) * 64 + row] = val.x * QSCALE;
        QsT[(dv + 1) * 64 + row] = val.y * QSCALE;
        QsT[(dv + 2) * 64 + row] = val.z * QSCALE;
        QsT[(dv + 3) * 64 + row] = val.w * QSCALE;
    }

    float m_i[4], l_i[4], o[4][4];
#pragma unroll
    for (int i = 0; i < 4; i++) {
        m_i[i] = -1e30f;
        l_i[i] = 0.f;
#pragma unroll
        for (int j = 0; j < 4; j++) o[i][j] = 0.f;
    }

    for (int kt = 0; kt < LKV / 64; kt++) {
        int j0 = kt * 64;
        const float *kb, *vb;
        long stride;
        if (j0 < LL) {
            kb = k + ((long)bb * LL + j0) * CC + hh * DH;
            vb = v + ((long)bb * LL + j0) * CC + hh * DH;
            stride = CC;
        } else {
            long off = ((long)(bh % BANK) * LPOOL + (j0 - LL)) * DH;
            kb = g_Kb + off;
            vb = g_Vb + off;
            stride = DH;
        }

        __syncthreads();
#pragma unroll
        for (int i = 0; i < 4; i++) {
            int idx = tid + i * 256;
            int row = idx >> 4;
            int dv  = (idx & 15) * 4;
            float4 kv4 = *(const float4*)(kb + (long)row * stride + dv);
            KsP[(dv + 0) * 64 + row] = kv4.x;
            KsP[(dv + 1) * 64 + row] = kv4.y;
            KsP[(dv + 2) * 64 + row] = kv4.z;
            KsP[(dv + 3) * 64 + row] = kv4.w;
            float4 vv4 = *(const float4*)(vb + (long)row * stride + dv);
            *(float4*)(&Vs[row * 64 + dv]) = vv4;
        }
        __syncthreads();

        float s[4][4];
#pragma unroll
        for (int i = 0; i < 4; i++)
#pragma unroll
            for (int j = 0; j < 4; j++) s[i][j] = 0.f;

#pragma unroll 16
        for (int d = 0; d < 64; d++) {
            float4 a = *(float4*)(&QsT[d * 64 + ty * 4]);
            float4 b = *(float4*)(&KsP[d * 64 + tx * 4]);
            float av[4] = {a.x, a.y, a.z, a.w};
            float bw[4] = {b.x, b.y, b.z, b.w};
#pragma unroll
            for (int i = 0; i < 4; i++)
#pragma unroll
                for (int j = 0; j < 4; j++)
                    s[i][j] = fmaf(av[i], bw[j], s[i][j]);
        }

        __syncthreads();   // done reading K^T before P overwrites it

#pragma unroll
        for (int i = 0; i < 4; i++) {
            float mx = fmaxf(fmaxf(s[i][0], s[i][1]), fmaxf(s[i][2], s[i][3]));
#pragma unroll
            for (int w = 1; w < 16; w <<= 1)
                mx = fmaxf(mx, __shfl_xor_sync(0xffffffffu, mx, w));
            float mnew = fmaxf(m_i[i], mx);
            float sc = __expf(m_i[i] - mnew);
            m_i[i] = mnew;

            float su = 0.f;
#pragma unroll
            for (int j = 0; j < 4; j++) {
                float p = __expf(s[i][j] - mnew);
                su += p;
                KsP[(ty * 4 + i) * 64 + tx * 4 + j] = p;
            }
#pragma unroll
            for (int w = 1; w < 16; w <<= 1)
                su += __shfl_xor_sync(0xffffffffu, su, w);
            l_i[i] = l_i[i] * sc + su;
#pragma unroll
            for (int j = 0; j < 4; j++) o[i][j] *= sc;
        }
        __syncthreads();

#pragma unroll 16
        for (int c = 0; c < 64; c++) {
            float p0 = KsP[(ty * 4 + 0) * 64 + c];
            float p1 = KsP[(ty * 4 + 1) * 64 + c];
            float p2 = KsP[(ty * 4 + 2) * 64 + c];
            float p3 = KsP[(ty * 4 + 3) * 64 + c];
            float4 vv = *(float4*)(&Vs[c * 64 + tx * 4]);
            float vw[4] = {vv.x, vv.y, vv.z, vv.w};
#pragma unroll
            for (int j = 0; j < 4; j++) {
                o[0][j] = fmaf(p0, vw[j], o[0][j]);
                o[1][j] = fmaf(p1, vw[j], o[1][j]);
                o[2][j] = fmaf(p2, vw[j], o[2][j]);
                o[3][j] = fmaf(p3, vw[j], o[3][j]);
            }
        }
    }

#pragma unroll
    for (int i = 0; i < 4; i++) {
        float inv = 1.f / l_i[i];
        int row = q0 + ty * 4 + i;
        float4 outv;
        outv.x = o[i][0] * inv;
        outv.y = o[i][1] * inv;
        outv.z = o[i][2] * inv;
        outv.w = o[i][3] * inv;
        *(float4*)(&ctx[((long)bb * LL + row) * CC + hh * DH + tx * 4]) = outv;
    }
}

// ---------------------------------------------------------------------------
extern "C" void kernel_launch(void* const* d_in, const int* in_sizes, int n_in,
                              void* d_out, int out_size) {
    const float* hs  = (const float*)d_in[0];
    const float* Wq  = (const float*)d_in[1];
    const float* Wk  = (const float*)d_in[2];
    const float* Wv  = (const float*)d_in[3];
    const float* Wo  = (const float*)d_in[4];
    const float* bo  = (const float*)d_in[5];
    const float* Kbg = (const float*)d_in[6];
    const float* Vbg = (const float*)d_in[7];
    float* out = (float*)d_out;

    float *gq, *gk, *gv, *gctx;
    cudaGetSymbolAddress((void**)&gq,   g_q);
    cudaGetSymbolAddress((void**)&gk,   g_k);
    cudaGetSymbolAddress((void**)&gv,   g_v);
    cudaGetSymbolAddress((void**)&gctx, g_ctx);

    // 1. Bank KV pool
    {
        int total = BANK * LPOOL * DH;
        pool_kernel<<<(total + 255) / 256, 256>>>(Kbg, Vbg);
    }

    // 2. QKV projections (tf32 tensor cores)
    {
        dim3 grid(CC / 128, (BB * LL) / 128);   // (10, 32)
        tgemm_kernel<<<grid, 256>>>(hs, Wq, nullptr, gq, BB * LL, CC, CC);
        tgemm_kernel<<<grid, 256>>>(hs, Wk, nullptr, gk, BB * LL, CC, CC);
        tgemm_kernel<<<grid, 256>>>(hs, Wv, nullptr, gv, BB * LL, CC, CC);
    }

    // 3. Flash attention (fp32, static 48KB smem)
    {
        dim3 grid(LL / 64, BHH);   // (16, 80)
        flash_kernel<<<grid, 256>>>(gq, gk, gv, gctx);
    }

    // 4. Output projection + bias (tf32 tensor cores)
    {
        dim3 grid(CC / 128, (BB * LL) / 128);
        tgemm_kernel<<<grid, 256>>>(gctx, Wo, bo, out, BB * LL, CC, CC);
    }
}

// round 8
// speedup vs baseline: 1.9057x; 1.2534x over previous
#include <cuda_runtime.h>
#include <cuda_fp16.h>
#include <cstdint>

// Problem constants
#define BB 4
#define LL 1024
#define CC 1280
#define HH 20
#define DH 64
#define BHH (BB*HH)        // 80
#define BANK 40
#define LPOOL 256          // (32/2)*(32/2)
#define LKV (LL + LPOOL)   // 1280
#define ALPHA_C 0.48f      // 0.8 * 0.6
#define QSCALE 0.125f      // 1/sqrt(64)

// Scratch (device globals are allowed; cudaMalloc is not)
__device__ float g_q[BB*LL*CC];
__device__ float g_k[BB*LL*CC];
__device__ float g_v[BB*LL*CC];
__device__ float g_ctx[BB*LL*CC];
__device__ float g_Kb[BANK*LPOOL*DH];
__device__ float g_Vb[BANK*LPOOL*DH];

__device__ __forceinline__ float fp16_round(float x) {
    return __half2float(__float2half_rn(x));
}

__device__ __forceinline__ unsigned f2tf32(float x) {
    unsigned r;
    asm("cvt.rna.tf32.f32 %0, %1;" : "=r"(r) : "f"(x));
    return r;
}

__device__ __forceinline__ void mma_tf32(float* d, const unsigned* a, const unsigned* b) {
    asm volatile(
        "mma.sync.aligned.m16n8k8.row.col.f32.tf32.tf32.f32 "
        "{%0,%1,%2,%3}, {%4,%5,%6,%7}, {%8,%9}, {%0,%1,%2,%3};\n"
        : "+f"(d[0]), "+f"(d[1]), "+f"(d[2]), "+f"(d[3])
        : "r"(a[0]), "r"(a[1]), "r"(a[2]), "r"(a[3]),
          "r"(b[0]), "r"(b[1]));
}

__device__ __forceinline__ void cp16(uint32_t saddr, const void* gptr) {
    asm volatile("cp.async.cg.shared.global [%0], [%1], 16;\n"
                 :: "r"(saddr), "l"(gptr));
}

// ---------------------------------------------------------------------------
// Bank KV preprocessing: fp16 round -> 2x2 avg pool over 32x32 grid -> *ALPHA
// ---------------------------------------------------------------------------
__global__ void pool_kernel(const float* __restrict__ Kg,
                            const float* __restrict__ Vg) {
    int idx = blockIdx.x * blockDim.x + threadIdx.x;
    const int total = BANK * LPOOL * DH;
    if (idx >= total) return;
    int d  = idx % DH;
    int p  = (idx / DH) % LPOOL;
    int bh = idx / (DH * LPOOL);
    int ph = p >> 4;          // /16
    int pw = p & 15;
    int t0 = (2 * ph) * 32 + 2 * pw;
    long base = ((long)bh * LL + t0) * DH + d;

    float ks = fp16_round(Kg[base])         + fp16_round(Kg[base + DH])
             + fp16_round(Kg[base + 32*DH]) + fp16_round(Kg[base + 33*DH]);
    float vs = fp16_round(Vg[base])         + fp16_round(Vg[base + DH])
             + fp16_round(Vg[base + 32*DH]) + fp16_round(Vg[base + 33*DH]);
    g_Kb[idx] = ALPHA_C * (ks * 0.25f);
    g_Vb[idx] = ALPHA_C * (vs * 0.25f);
}

// ---------------------------------------------------------------------------
// tf32 tensor-core GEMM, 2-stage cp.async pipeline, optionally fused over
// up to 3 weight matrices (selected by blockIdx.x / n-tiles).
// Block 128x128, BK=16, 256 threads = 8 warps (2m x 4n), warp tile 64x32.
// Smem fp32 (tf32 cvt at fragment load). ASTR=20, BSTR=132: conflict-free.
// ---------------------------------------------------------------------------
#define BKP 16
#define ASTRP 20
#define BSTRP 132
#define NTN (CC/128)   // 10 n-tiles per matrix

__global__ __launch_bounds__(256)
void tgemm_kernel(const float* __restrict__ A,
                  const float* __restrict__ W0, const float* __restrict__ W1,
                  const float* __restrict__ W2, const float* __restrict__ bias,
                  float* __restrict__ C0, float* __restrict__ C1,
                  float* __restrict__ C2, int M, int N, int K) {
    __shared__ float As[2][128 * ASTRP];
    __shared__ float Bs[2][BKP * BSTRP];

    int tid  = threadIdx.x;
    int lane = tid & 31;
    int wid  = tid >> 5;
    int wm   = wid >> 2;          // 0..1
    int wn   = wid & 3;           // 0..3
    int g    = lane >> 3 ? 0 : 0; // placeholder
    g        = lane >> 2;         // 0..7
    int tg   = lane & 3;          // 0..3

    int mat = blockIdx.x / NTN;
    int ntile = blockIdx.x % NTN;
    const float* W = (mat == 0) ? W0 : (mat == 1) ? W1 : W2;
    float* C       = (mat == 0) ? C0 : (mat == 1) ? C1 : C2;

    int m0 = blockIdx.y * 128;
    int n0 = ntile * 128;

    // load mappings
    int arow  = tid >> 1;             // 0..127
    int akseg = (tid & 1) * 8;        // 0 or 8, +{0,4}
    int brow  = tid >> 4;             // 0..15
    int bcol  = (tid & 15) * 8;       // 0..120, +{0,4}

    uint32_t as_u = (uint32_t)__cvta_generic_to_shared(&As[0][0]);
    uint32_t bs_u = (uint32_t)__cvta_generic_to_shared(&Bs[0][0]);

    const float* agp = A + (long)(m0 + arow) * K + akseg;
    const float* bgp = W + (long)brow * N + n0 + bcol;
    uint32_t asw = as_u + (uint32_t)(arow * ASTRP + akseg) * 4u;
    uint32_t bsw = bs_u + (uint32_t)(brow * BSTRP + bcol) * 4u;
    const uint32_t abuf = 128 * ASTRP * 4u;
    const uint32_t bbuf = BKP * BSTRP * 4u;

    float acc[4][4][4];
#pragma unroll
    for (int i = 0; i < 4; i++)
#pragma unroll
        for (int j = 0; j < 4; j++)
#pragma unroll
            for (int r = 0; r < 4; r++) acc[i][j][r] = 0.f;

    const int NT = K / BKP;     // 80

    // prefetch tile 0 into buf 0
    cp16(asw,          agp);
    cp16(asw + 16,     agp + 4);
    cp16(bsw,          bgp);
    cp16(bsw + 16,     bgp + 4);
    asm volatile("cp.async.commit_group;\n");

    for (int t = 0; t < NT; t++) {
        int cur = t & 1;
        if (t + 1 < NT) {
            int nxt = cur ^ 1;
            const float* ag = agp + (t + 1) * BKP;
            const float* bg = bgp + (long)(t + 1) * BKP * N;
            cp16(asw + nxt * abuf,      ag);
            cp16(asw + nxt * abuf + 16, ag + 4);
            cp16(bsw + nxt * bbuf,      bg);
            cp16(bsw + nxt * bbuf + 16, bg + 4);
            asm volatile("cp.async.commit_group;\n");
            asm volatile("cp.async.wait_group 1;\n");
        } else {
            asm volatile("cp.async.wait_group 0;\n");
        }
        __syncthreads();

        const float* Ac = &As[cur][0];
        const float* Bc = &Bs[cur][0];
#pragma unroll
        for (int kk = 0; kk < BKP; kk += 8) {
            unsigned af[4][4], bf[4][2];
#pragma unroll
            for (int mf = 0; mf < 4; mf++) {
                int r = wm * 64 + mf * 16;
                af[mf][0] = f2tf32(Ac[(r + g    ) * ASTRP + kk + tg    ]);
                af[mf][1] = f2tf32(Ac[(r + g + 8) * ASTRP + kk + tg    ]);
                af[mf][2] = f2tf32(Ac[(r + g    ) * ASTRP + kk + tg + 4]);
                af[mf][3] = f2tf32(Ac[(r + g + 8) * ASTRP + kk + tg + 4]);
            }
#pragma unroll
            for (int nf = 0; nf < 4; nf++) {
                int c = wn * 32 + nf * 8 + g;
                bf[nf][0] = f2tf32(Bc[(kk + tg    ) * BSTRP + c]);
                bf[nf][1] = f2tf32(Bc[(kk + tg + 4) * BSTRP + c]);
            }
#pragma unroll
            for (int mf = 0; mf < 4; mf++)
#pragma unroll
                for (int nf = 0; nf < 4; nf++)
                    mma_tf32(acc[mf][nf], af[mf], bf[nf]);
        }
        __syncthreads();
    }

    // Epilogue
#pragma unroll
    for (int mf = 0; mf < 4; mf++) {
        long r0 = m0 + wm * 64 + mf * 16 + g;
#pragma unroll
        for (int nf = 0; nf < 4; nf++) {
            int c = n0 + wn * 32 + nf * 8 + tg * 2;
            float b0 = bias ? bias[c] : 0.f;
            float b1 = bias ? bias[c + 1] : 0.f;
            float2 v0 = {acc[mf][nf][0] + b0, acc[mf][nf][1] + b1};
            float2 v1 = {acc[mf][nf][2] + b0, acc[mf][nf][3] + b1};
            *(float2*)(C + r0 * N + c)       = v0;
            *(float2*)(C + (r0 + 8) * N + c) = v1;
        }
    }
}

// ---------------------------------------------------------------------------
// Flash attention: per block = (one head, 64 q rows), kv len = 1280
// Static smem 48KB exactly: QsT[64][64], KsP[64][64] (K^T, reused for P), Vs[64][64]
// ---------------------------------------------------------------------------
__global__ __launch_bounds__(256)
void flash_kernel(const float* __restrict__ q, const float* __restrict__ k,
                  const float* __restrict__ v, float* __restrict__ ctx) {
    __shared__ float QsT[64 * 64];   // d-major
    __shared__ float KsP[64 * 64];   // d-major K^T; reused as P [q][kv]
    __shared__ float Vs[64 * 64];    // row-major

    int tid = threadIdx.x;
    int tx = tid & 15;
    int ty = tid >> 4;
    int bh = blockIdx.y;
    int bb = bh / HH;
    int hh = bh % HH;
    int q0 = blockIdx.x * 64;

    const float* qbase = q + ((long)bb * LL + q0) * CC + hh * DH;

#pragma unroll
    for (int i = 0; i < 4; i++) {
        int idx = tid + i * 256;
        int row = idx >> 4;
        int dv  = (idx & 15) * 4;
        float4 val = *(const float4*)(qbase + (long)row * CC + dv);
        QsT[(dv + 0) * 64 + row] = val.x * QSCALE;
        QsT[(dv + 1) * 64 + row] = val.y * QSCALE;
        QsT[(dv + 2) * 64 + row] = val.z * QSCALE;
        QsT[(dv + 3) * 64 + row] = val.w * QSCALE;
    }

    float m_i[4], l_i[4], o[4][4];
#pragma unroll
    for (int i = 0; i < 4; i++) {
        m_i[i] = -1e30f;
        l_i[i] = 0.f;
#pragma unroll
        for (int j = 0; j < 4; j++) o[i][j] = 0.f;
    }

    for (int kt = 0; kt < LKV / 64; kt++) {
        int j0 = kt * 64;
        const float *kb, *vb;
        long stride;
        if (j0 < LL) {
            kb = k + ((long)bb * LL + j0) * CC + hh * DH;
            vb = v + ((long)bb * LL + j0) * CC + hh * DH;
            stride = CC;
        } else {
            long off = ((long)(bh % BANK) * LPOOL + (j0 - LL)) * DH;
            kb = g_Kb + off;
            vb = g_Vb + off;
            stride = DH;
        }

        __syncthreads();
#pragma unroll
        for (int i = 0; i < 4; i++) {
            int idx = tid + i * 256;
            int row = idx >> 4;
            int dv  = (idx & 15) * 4;
            float4 kv4 = *(const float4*)(kb + (long)row * stride + dv);
            KsP[(dv + 0) * 64 + row] = kv4.x;
            KsP[(dv + 1) * 64 + row] = kv4.y;
            KsP[(dv + 2) * 64 + row] = kv4.z;
            KsP[(dv + 3) * 64 + row] = kv4.w;
            float4 vv4 = *(const float4*)(vb + (long)row * stride + dv);
            *(float4*)(&Vs[row * 64 + dv]) = vv4;
        }
        __syncthreads();

        float s[4][4];
#pragma unroll
        for (int i = 0; i < 4; i++)
#pragma unroll
            for (int j = 0; j < 4; j++) s[i][j] = 0.f;

#pragma unroll 16
        for (int d = 0; d < 64; d++) {
            float4 a = *(float4*)(&QsT[d * 64 + ty * 4]);
            float4 b = *(float4*)(&KsP[d * 64 + tx * 4]);
            float av[4] = {a.x, a.y, a.z, a.w};
            float bw[4] = {b.x, b.y, b.z, b.w};
#pragma unroll
            for (int i = 0; i < 4; i++)
#pragma unroll
                for (int j = 0; j < 4; j++)
                    s[i][j] = fmaf(av[i], bw[j], s[i][j]);
        }

        __syncthreads();   // done reading K^T before P overwrites it

#pragma unroll
        for (int i = 0; i < 4; i++) {
            float mx = fmaxf(fmaxf(s[i][0], s[i][1]), fmaxf(s[i][2], s[i][3]));
#pragma unroll
            for (int w = 1; w < 16; w <<= 1)
                mx = fmaxf(mx, __shfl_xor_sync(0xffffffffu, mx, w));
            float mnew = fmaxf(m_i[i], mx);
            float sc = __expf(m_i[i] - mnew);
            m_i[i] = mnew;

            float su = 0.f;
#pragma unroll
            for (int j = 0; j < 4; j++) {
                float p = __expf(s[i][j] - mnew);
                su += p;
                KsP[(ty * 4 + i) * 64 + tx * 4 + j] = p;
            }
#pragma unroll
            for (int w = 1; w < 16; w <<= 1)
                su += __shfl_xor_sync(0xffffffffu, su, w);
            l_i[i] = l_i[i] * sc + su;
#pragma unroll
            for (int j = 0; j < 4; j++) o[i][j] *= sc;
        }
        __syncthreads();

#pragma unroll 16
        for (int c = 0; c < 64; c++) {
            float p0 = KsP[(ty * 4 + 0) * 64 + c];
            float p1 = KsP[(ty * 4 + 1) * 64 + c];
            float p2 = KsP[(ty * 4 + 2) * 64 + c];
            float p3 = KsP[(ty * 4 + 3) * 64 + c];
            float4 vv = *(float4*)(&Vs[c * 64 + tx * 4]);
            float vw[4] = {vv.x, vv.y, vv.z, vv.w};
#pragma unroll
            for (int j = 0; j < 4; j++) {
                o[0][j] = fmaf(p0, vw[j], o[0][j]);
                o[1][j] = fmaf(p1, vw[j], o[1][j]);
                o[2][j] = fmaf(p2, vw[j], o[2][j]);
                o[3][j] = fmaf(p3, vw[j], o[3][j]);
            }
        }
    }

#pragma unroll
    for (int i = 0; i < 4; i++) {
        float inv = 1.f / l_i[i];
        int row = q0 + ty * 4 + i;
        float4 outv;
        outv.x = o[i][0] * inv;
        outv.y = o[i][1] * inv;
        outv.z = o[i][2] * inv;
        outv.w = o[i][3] * inv;
        *(float4*)(&ctx[((long)bb * LL + row) * CC + hh * DH + tx * 4]) = outv;
    }
}

// ---------------------------------------------------------------------------
extern "C" void kernel_launch(void* const* d_in, const int* in_sizes, int n_in,
                              void* d_out, int out_size) {
    const float* hs  = (const float*)d_in[0];
    const float* Wq  = (const float*)d_in[1];
    const float* Wk  = (const float*)d_in[2];
    const float* Wv  = (const float*)d_in[3];
    const float* Wo  = (const float*)d_in[4];
    const float* bo  = (const float*)d_in[5];
    const float* Kbg = (const float*)d_in[6];
    const float* Vbg = (const float*)d_in[7];
    float* out = (float*)d_out;

    float *gq, *gk, *gv, *gctx;
    cudaGetSymbolAddress((void**)&gq,   g_q);
    cudaGetSymbolAddress((void**)&gk,   g_k);
    cudaGetSymbolAddress((void**)&gv,   g_v);
    cudaGetSymbolAddress((void**)&gctx, g_ctx);

    // 1. Bank KV pool
    {
        int total = BANK * LPOOL * DH;
        pool_kernel<<<(total + 255) / 256, 256>>>(Kbg, Vbg);
    }

    // 2. Fused QKV projections (tf32 tensor cores, cp.async pipeline)
    {
        dim3 grid(3 * NTN, (BB * LL) / 128);   // (30, 32) = 960 blocks
        tgemm_kernel<<<grid, 256>>>(hs, Wq, Wk, Wv, nullptr,
                                    gq, gk, gv, BB * LL, CC, CC);
    }

    // 3. Flash attention (fp32, static 48KB smem)
    {
        dim3 grid(LL / 64, BHH);   // (16, 80)
        flash_kernel<<<grid, 256>>>(gq, gk, gv, gctx);
    }

    // 4. Output projection + bias (tf32 tensor cores)
    {
        dim3 grid(NTN, (BB * LL) / 128);       // (10, 32)
        tgemm_kernel<<<grid, 256>>>(gctx, Wo, Wo, Wo, bo,
                                    out, out, out, BB * LL, CC, CC);
    }
}

// round 9
// speedup vs baseline: 4.4609x; 2.3408x over previous
#include <cuda_runtime.h>
#include <cuda_fp16.h>
#include <cstdint>

// Problem constants
#define BB 4
#define LL 1024
#define CC 1280
#define HH 20
#define DH 64
#define BHH (BB*HH)        // 80
#define BANK 40
#define LPOOL 256          // (32/2)*(32/2)
#define LKV (LL + LPOOL)   // 1280
#define ALPHA_C 0.48f      // 0.8 * 0.6
#define QSCALE 0.125f      // 1/sqrt(64)
#define LOG2E 1.4426950408889634f

// Scratch (device globals are allowed; cudaMalloc is not)
__device__ float  g_q[BB*LL*CC];
__device__ float  g_ctx[BB*LL*CC];
__device__ __half g_kh[(size_t)BHH*LKV*DH];   // fused main+bank K, fp16 head-major
__device__ __half g_vh[(size_t)BHH*LKV*DH];

__device__ __forceinline__ float fp16_round(float x) {
    return __half2float(__float2half_rn(x));
}
__device__ __forceinline__ unsigned f2tf32(float x) {
    unsigned r;
    asm("cvt.rna.tf32.f32 %0, %1;" : "=r"(r) : "f"(x));
    return r;
}
__device__ __forceinline__ float ex2f(float x) {
    float y;
    asm("ex2.approx.ftz.f32 %0, %1;" : "=f"(y) : "f"(x));
    return y;
}
__device__ __forceinline__ void mma_tf32(float* d, const unsigned* a, const unsigned* b) {
    asm volatile(
        "mma.sync.aligned.m16n8k8.row.col.f32.tf32.tf32.f32 "
        "{%0,%1,%2,%3}, {%4,%5,%6,%7}, {%8,%9}, {%0,%1,%2,%3};\n"
        : "+f"(d[0]), "+f"(d[1]), "+f"(d[2]), "+f"(d[3])
        : "r"(a[0]), "r"(a[1]), "r"(a[2]), "r"(a[3]),
          "r"(b[0]), "r"(b[1]));
}
__device__ __forceinline__ void mma_f16(float* d, const unsigned* a, unsigned b0, unsigned b1) {
    asm volatile(
        "mma.sync.aligned.m16n8k16.row.col.f32.f16.f16.f32 "
        "{%0,%1,%2,%3}, {%4,%5,%6,%7}, {%8,%9}, {%0,%1,%2,%3};\n"
        : "+f"(d[0]), "+f"(d[1]), "+f"(d[2]), "+f"(d[3])
        : "r"(a[0]), "r"(a[1]), "r"(a[2]), "r"(a[3]),
          "r"(b0), "r"(b1));
}
__device__ __forceinline__ void cp16(uint32_t saddr, const void* gptr) {
    asm volatile("cp.async.cg.shared.global [%0], [%1], 16;\n"
                 :: "r"(saddr), "l"(gptr));
}
__device__ __forceinline__ void ldsm_x4(unsigned& r0, unsigned& r1, unsigned& r2,
                                        unsigned& r3, uint32_t a) {
    asm volatile("ldmatrix.sync.aligned.m8n8.x4.shared.b16 {%0,%1,%2,%3}, [%4];\n"
                 : "=r"(r0), "=r"(r1), "=r"(r2), "=r"(r3) : "r"(a));
}
__device__ __forceinline__ void ldsm_x4_t(unsigned& r0, unsigned& r1, unsigned& r2,
                                          unsigned& r3, uint32_t a) {
    asm volatile("ldmatrix.sync.aligned.m8n8.x4.trans.shared.b16 {%0,%1,%2,%3}, [%4];\n"
                 : "=r"(r0), "=r"(r1), "=r"(r2), "=r"(r3) : "r"(a));
}

// ---------------------------------------------------------------------------
// Bank KV: fp16 round -> 2x2 avg pool -> *ALPHA, write fp16 rows [1024..1279]
// of g_kh/g_vh for BOTH bh and bh+40 (bank repeats across batch).
// ---------------------------------------------------------------------------
__global__ void pool_kernel(const float* __restrict__ Kg,
                            const float* __restrict__ Vg) {
    int idx = blockIdx.x * blockDim.x + threadIdx.x;
    const int total = BANK * LPOOL * DH;
    if (idx >= total) return;
    int d  = idx % DH;
    int p  = (idx / DH) % LPOOL;
    int bh = idx / (DH * LPOOL);
    int ph = p >> 4;
    int pw = p & 15;
    int t0 = (2 * ph) * 32 + 2 * pw;
    long base = ((long)bh * LL + t0) * DH + d;

    float ks = fp16_round(Kg[base])         + fp16_round(Kg[base + DH])
             + fp16_round(Kg[base + 32*DH]) + fp16_round(Kg[base + 33*DH]);
    float vs = fp16_round(Vg[base])         + fp16_round(Vg[base + DH])
             + fp16_round(Vg[base + 32*DH]) + fp16_round(Vg[base + 33*DH]);
    __half kq = __float2half(ALPHA_C * (ks * 0.25f));
    __half vq = __float2half(ALPHA_C * (vs * 0.25f));
#pragma unroll
    for (int rep = 0; rep < 2; rep++) {
        long dst = ((long)(bh + rep * BANK) * LKV + LL + p) * DH + d;
        g_kh[dst] = kq;
        g_vh[dst] = vq;
    }
}

// ---------------------------------------------------------------------------
// tf32 tensor-core GEMM, 2-stage cp.async pipeline, fused over up to 3 W.
// mat==0 -> fp32 C0 (+bias); mat==1/2 -> fp16 head-major g_kh/g_vh layout.
// ---------------------------------------------------------------------------
#define BKP 16
#define ASTRP 20
#define BSTRP 132
#define NTN (CC/128)   // 10 n-tiles per matrix

__global__ __launch_bounds__(256)
void tgemm_kernel(const float* __restrict__ A,
                  const float* __restrict__ W0, const float* __restrict__ W1,
                  const float* __restrict__ W2, const float* __restrict__ bias,
                  float* __restrict__ C0, __half* __restrict__ HK,
                  __half* __restrict__ HV, int M, int N, int K) {
    __shared__ float As[2][128 * ASTRP];
    __shared__ float Bs[2][BKP * BSTRP];

    int tid  = threadIdx.x;
    int lane = tid & 31;
    int wid  = tid >> 5;
    int wm   = wid >> 2;
    int wn   = wid & 3;
    int g    = lane >> 2;
    int tg   = lane & 3;

    int mat = blockIdx.x / NTN;
    int ntile = blockIdx.x % NTN;
    const float* W = (mat == 0) ? W0 : (mat == 1) ? W1 : W2;

    int m0 = blockIdx.y * 128;
    int n0 = ntile * 128;

    int arow  = tid >> 1;
    int akseg = (tid & 1) * 8;
    int brow  = tid >> 4;
    int bcol  = (tid & 15) * 8;

    uint32_t as_u = (uint32_t)__cvta_generic_to_shared(&As[0][0]);
    uint32_t bs_u = (uint32_t)__cvta_generic_to_shared(&Bs[0][0]);

    const float* agp = A + (long)(m0 + arow) * K + akseg;
    const float* bgp = W + (long)brow * N + n0 + bcol;
    uint32_t asw = as_u + (uint32_t)(arow * ASTRP + akseg) * 4u;
    uint32_t bsw = bs_u + (uint32_t)(brow * BSTRP + bcol) * 4u;
    const uint32_t abuf = 128 * ASTRP * 4u;
    const uint32_t bbuf = BKP * BSTRP * 4u;

    float acc[4][4][4];
#pragma unroll
    for (int i = 0; i < 4; i++)
#pragma unroll
        for (int j = 0; j < 4; j++)
#pragma unroll
            for (int r = 0; r < 4; r++) acc[i][j][r] = 0.f;

    const int NT = K / BKP;

    cp16(asw,      agp);
    cp16(asw + 16, agp + 4);
    cp16(bsw,      bgp);
    cp16(bsw + 16, bgp + 4);
    asm volatile("cp.async.commit_group;\n");

    for (int t = 0; t < NT; t++) {
        int cur = t & 1;
        if (t + 1 < NT) {
            int nxt = cur ^ 1;
            const float* ag = agp + (t + 1) * BKP;
            const float* bg = bgp + (long)(t + 1) * BKP * N;
            cp16(asw + nxt * abuf,      ag);
            cp16(asw + nxt * abuf + 16, ag + 4);
            cp16(bsw + nxt * bbuf,      bg);
            cp16(bsw + nxt * bbuf + 16, bg + 4);
            asm volatile("cp.async.commit_group;\n");
            asm volatile("cp.async.wait_group 1;\n");
        } else {
            asm volatile("cp.async.wait_group 0;\n");
        }
        __syncthreads();

        const float* Ac = &As[cur][0];
        const float* Bc = &Bs[cur][0];
#pragma unroll
        for (int kk = 0; kk < BKP; kk += 8) {
            unsigned af[4][4], bf[4][2];
#pragma unroll
            for (int mf = 0; mf < 4; mf++) {
                int r = wm * 64 + mf * 16;
                af[mf][0] = f2tf32(Ac[(r + g    ) * ASTRP + kk + tg    ]);
                af[mf][1] = f2tf32(Ac[(r + g + 8) * ASTRP + kk + tg    ]);
                af[mf][2] = f2tf32(Ac[(r + g    ) * ASTRP + kk + tg + 4]);
                af[mf][3] = f2tf32(Ac[(r + g + 8) * ASTRP + kk + tg + 4]);
            }
#pragma unroll
            for (int nf = 0; nf < 4; nf++) {
                int c = wn * 32 + nf * 8 + g;
                bf[nf][0] = f2tf32(Bc[(kk + tg    ) * BSTRP + c]);
                bf[nf][1] = f2tf32(Bc[(kk + tg + 4) * BSTRP + c]);
            }
#pragma unroll
            for (int mf = 0; mf < 4; mf++)
#pragma unroll
                for (int nf = 0; nf < 4; nf++)
                    mma_tf32(acc[mf][nf], af[mf], bf[nf]);
        }
        __syncthreads();
    }

    // Epilogue
    if (mat == 0) {
#pragma unroll
        for (int mf = 0; mf < 4; mf++) {
            long r0 = m0 + wm * 64 + mf * 16 + g;
#pragma unroll
            for (int nf = 0; nf < 4; nf++) {
                int c = n0 + wn * 32 + nf * 8 + tg * 2;
                float b0 = bias ? bias[c] : 0.f;
                float b1 = bias ? bias[c + 1] : 0.f;
                float2 v0 = {acc[mf][nf][0] + b0, acc[mf][nf][1] + b1};
                float2 v1 = {acc[mf][nf][2] + b0, acc[mf][nf][3] + b1};
                *(float2*)(C0 + r0 * N + c)       = v0;
                *(float2*)(C0 + (r0 + 8) * N + c) = v1;
            }
        }
    } else {
        __half* H = (mat == 1) ? HK : HV;
#pragma unroll
        for (int mf = 0; mf < 4; mf++) {
            int r0 = m0 + wm * 64 + mf * 16 + g;
#pragma unroll
            for (int nf = 0; nf < 4; nf++) {
                int c = n0 + wn * 32 + nf * 8 + tg * 2;
                int h = c >> 6, d = c & 63;
#pragma unroll
                for (int rr = 0; rr < 2; rr++) {
                    int row = r0 + rr * 8;
                    int b = row >> 10, l = row & 1023;
                    long dst = ((long)(b * HH + h) * LKV + l) * DH + d;
                    __half2 hv = __floats2half2_rn(acc[mf][nf][rr * 2],
                                                   acc[mf][nf][rr * 2 + 1]);
                    *(__half2*)(&H[dst]) = hv;
                }
            }
        }
    }
}

// ---------------------------------------------------------------------------
// Flash attention, fp16 tensor cores. Block = (head, 128 q rows), 8 warps,
// each warp owns 16 q rows. KV tiles of 64, double-buffered cp.async.
// Smem: K,V [64][72] fp16 x2 buffers = 36864 B.
// ---------------------------------------------------------------------------
#define KPAD 72
#define KVT  (64 * KPAD)

__global__ __launch_bounds__(256)
void flash_tc_kernel(const float* __restrict__ q, const __half* __restrict__ kh,
                     const __half* __restrict__ vh, float* __restrict__ ctx) {
    __shared__ __half sKV[2][2][KVT];   // [buf][0=K,1=V]

    int tid  = threadIdx.x;
    int lane = tid & 31;
    int w    = tid >> 5;
    int g    = lane >> 2;
    int tg   = lane & 3;
    int bh = blockIdx.y;
    int bb = bh / HH;
    int hh = bh % HH;
    int q0 = blockIdx.x * 128;
    int qrow = q0 + w * 16 + g;

    // Q fragments from gmem, scaled by QSCALE*log2e (log2-domain softmax)
    const float sca = QSCALE * LOG2E;
    unsigned qa[4][4];
    {
        const float* qp = q + ((long)bb * LL + qrow) * CC + hh * DH;
#pragma unroll
        for (int t = 0; t < 4; t++) {
            float2 x0 = *(const float2*)(qp + 16 * t + 2 * tg);
            float2 x1 = *(const float2*)(qp + 8 * CC + 16 * t + 2 * tg);
            float2 x2 = *(const float2*)(qp + 16 * t + 8 + 2 * tg);
            float2 x3 = *(const float2*)(qp + 8 * CC + 16 * t + 8 + 2 * tg);
            __half2 h0 = __floats2half2_rn(x0.x * sca, x0.y * sca);
            __half2 h1 = __floats2half2_rn(x1.x * sca, x1.y * sca);
            __half2 h2 = __floats2half2_rn(x2.x * sca, x2.y * sca);
            __half2 h3 = __floats2half2_rn(x3.x * sca, x3.y * sca);
            qa[t][0] = *(unsigned*)&h0;
            qa[t][1] = *(unsigned*)&h1;
            qa[t][2] = *(unsigned*)&h2;
            qa[t][3] = *(unsigned*)&h3;
        }
    }

    // cp.async load mapping: 256 threads, tensor = tid>>7, 2 threads/row
    int tsel = tid >> 7;
    int idxl = tid & 127;
    int lrow = idxl >> 1;
    int lhf  = idxl & 1;          // half-row: cols 0-31 or 32-63
    const __half* gsrc0 = (tsel ? vh : kh) + ((long)bh * LKV) * DH
                        + lrow * DH + lhf * 32;
    uint32_t sdst0 = (uint32_t)__cvta_generic_to_shared(&sKV[0][tsel][0])
                   + (uint32_t)(lrow * KPAD + lhf * 32) * 2u;
    const uint32_t bufstep = 2u * KVT * 2u;   // bytes between buffers

    float m0v = -1e30f, m1v = -1e30f, l0 = 0.f, l1 = 0.f;
    float O[8][4];
#pragma unroll
    for (int j = 0; j < 8; j++)
#pragma unroll
        for (int r = 0; r < 4; r++) O[j][r] = 0.f;

    const int NT = LKV / 64;   // 20

    // prefetch tile 0
    {
        const __half* s = gsrc0;
#pragma unroll
        for (int i = 0; i < 4; i++) cp16(sdst0 + i * 16, s + i * 8);
        asm volatile("cp.async.commit_group;\n");
    }

    for (int t = 0; t < NT; t++) {
        int cur = t & 1;
        if (t + 1 < NT) {
            const __half* s = gsrc0 + (long)(t + 1) * 64 * DH;
            uint32_t dd = sdst0 + (cur ^ 1) * bufstep;
#pragma unroll
            for (int i = 0; i < 4; i++) cp16(dd + i * 16, s + i * 8);
            asm volatile("cp.async.commit_group;\n");
            asm volatile("cp.async.wait_group 1;\n");
        } else {
            asm volatile("cp.async.wait_group 0;\n");
        }
        __syncthreads();

        uint32_t kbase = (uint32_t)__cvta_generic_to_shared(&sKV[cur][0][0]);
        uint32_t vbase = (uint32_t)__cvta_generic_to_shared(&sKV[cur][1][0]);
        int mm = lane >> 3;
        int r5 = lane & 7;

        // S = Q K^T (log2 domain)
        float sacc[8][4];
#pragma unroll
        for (int j = 0; j < 8; j++)
#pragma unroll
            for (int r = 0; r < 4; r++) sacc[j][r] = 0.f;

#pragma unroll
        for (int tt = 0; tt < 4; tt++) {
#pragma unroll
            for (int j2 = 0; j2 < 4; j2++) {
                unsigned b0, b1, b2, b3;
                uint32_t a = kbase +
                    (uint32_t)(((j2 * 16 + (mm >> 1) * 8 + r5) * KPAD
                                + tt * 16 + (mm & 1) * 8) * 2);
                ldsm_x4(b0, b1, b2, b3, a);
                mma_f16(sacc[2 * j2],     qa[tt], b0, b1);
                mma_f16(sacc[2 * j2 + 1], qa[tt], b2, b3);
            }
        }

        // Online softmax (rows g and g+8)
        float mx0 = -1e30f, mx1 = -1e30f;
#pragma unroll
        for (int j = 0; j < 8; j++) {
            mx0 = fmaxf(mx0, fmaxf(sacc[j][0], sacc[j][1]));
            mx1 = fmaxf(mx1, fmaxf(sacc[j][2], sacc[j][3]));
        }
        mx0 = fmaxf(mx0, __shfl_xor_sync(0xffffffffu, mx0, 1));
        mx0 = fmaxf(mx0, __shfl_xor_sync(0xffffffffu, mx0, 2));
        mx1 = fmaxf(mx1, __shfl_xor_sync(0xffffffffu, mx1, 1));
        mx1 = fmaxf(mx1, __shfl_xor_sync(0xffffffffu, mx1, 2));

        float mn0 = fmaxf(m0v, mx0);
        float mn1 = fmaxf(m1v, mx1);
        float sc0 = ex2f(m0v - mn0);
        float sc1 = ex2f(m1v - mn1);
        m0v = mn0; m1v = mn1;

        float pex[8][4];
        float su0 = 0.f, su1 = 0.f;
#pragma unroll
        for (int j = 0; j < 8; j++) {
            pex[j][0] = ex2f(sacc[j][0] - mn0);
            pex[j][1] = ex2f(sacc[j][1] - mn0);
            pex[j][2] = ex2f(sacc[j][2] - mn1);
            pex[j][3] = ex2f(sacc[j][3] - mn1);
            su0 += pex[j][0] + pex[j][1];
            su1 += pex[j][2] + pex[j][3];
        }
        su0 += __shfl_xor_sync(0xffffffffu, su0, 1);
        su0 += __shfl_xor_sync(0xffffffffu, su0, 2);
        su1 += __shfl_xor_sync(0xffffffffu, su1, 1);
        su1 += __shfl_xor_sync(0xffffffffu, su1, 2);
        l0 = l0 * sc0 + su0;
        l1 = l1 * sc1 + su1;

#pragma unroll
        for (int j = 0; j < 8; j++) {
            O[j][0] *= sc0; O[j][1] *= sc0;
            O[j][2] *= sc1; O[j][3] *= sc1;
        }

        // Pack P fragments directly from accumulators (C layout == A layout)
        unsigned paf[4][4];
#pragma unroll
        for (int tt = 0; tt < 4; tt++) {
            __half2 a0 = __floats2half2_rn(pex[2*tt][0],   pex[2*tt][1]);
            __half2 a1 = __floats2half2_rn(pex[2*tt][2],   pex[2*tt][3]);
            __half2 a2 = __floats2half2_rn(pex[2*tt+1][0], pex[2*tt+1][1]);
            __half2 a3 = __floats2half2_rn(pex[2*tt+1][2], pex[2*tt+1][3]);
            paf[tt][0] = *(unsigned*)&a0;
            paf[tt][1] = *(unsigned*)&a1;
            paf[tt][2] = *(unsigned*)&a2;
            paf[tt][3] = *(unsigned*)&a3;
        }

        // O += P V  (V^T fragments via ldmatrix.trans)
#pragma unroll
        for (int tt = 0; tt < 4; tt++) {
#pragma unroll
            for (int j2 = 0; j2 < 4; j2++) {
                unsigned b0, b1, b2, b3;
                uint32_t a = vbase +
                    (uint32_t)(((tt * 16 + (mm & 1) * 8 + r5) * KPAD
                                + j2 * 16 + (mm >> 1) * 8) * 2);
                ldsm_x4_t(b0, b1, b2, b3, a);
                mma_f16(O[2 * j2],     paf[tt], b0, b1);
                mma_f16(O[2 * j2 + 1], paf[tt], b2, b3);
            }
        }
        __syncthreads();
    }

    // Normalize + write ctx [B, L, H*Dh]
    float inv0 = 1.f / l0;
    float inv1 = 1.f / l1;
    float* cp0 = ctx + ((long)bb * LL + qrow) * CC + hh * DH;
#pragma unroll
    for (int j = 0; j < 8; j++) {
        float2 v0 = {O[j][0] * inv0, O[j][1] * inv0};
        float2 v1 = {O[j][2] * inv1, O[j][3] * inv1};
        *(float2*)(cp0 + 8 * j + 2 * tg)          = v0;
        *(float2*)(cp0 + 8 * CC + 8 * j + 2 * tg) = v1;
    }
}

// ---------------------------------------------------------------------------
extern "C" void kernel_launch(void* const* d_in, const int* in_sizes, int n_in,
                              void* d_out, int out_size) {
    const float* hs  = (const float*)d_in[0];
    const float* Wq  = (const float*)d_in[1];
    const float* Wk  = (const float*)d_in[2];
    const float* Wv  = (const float*)d_in[3];
    const float* Wo  = (const float*)d_in[4];
    const float* bo  = (const float*)d_in[5];
    const float* Kbg = (const float*)d_in[6];
    const float* Vbg = (const float*)d_in[7];
    float* out = (float*)d_out;

    float *gq, *gctx;
    __half *gkh, *gvh;
    cudaGetSymbolAddress((void**)&gq,   g_q);
    cudaGetSymbolAddress((void**)&gctx, g_ctx);
    cudaGetSymbolAddress((void**)&gkh,  g_kh);
    cudaGetSymbolAddress((void**)&gvh,  g_vh);

    // 1. Bank KV pool -> fp16 rows [1024..1280) of g_kh/g_vh
    {
        int total = BANK * LPOOL * DH;
        pool_kernel<<<(total + 255) / 256, 256>>>(Kbg, Vbg);
    }

    // 2. Fused QKV projections; K/V epilogue writes fp16 head-major directly
    {
        dim3 grid(3 * NTN, (BB * LL) / 128);   // (30, 32)
        tgemm_kernel<<<grid, 256>>>(hs, Wq, Wk, Wv, nullptr,
                                    gq, gkh, gvh, BB * LL, CC, CC);
    }

    // 3. Flash attention on fp16 tensor cores
    {
        dim3 grid(LL / 128, BHH);   // (8, 80)
        flash_tc_kernel<<<grid, 256>>>(gq, gkh, gvh, gctx);
    }

    // 4. Output projection + bias (tf32)
    {
        dim3 grid(NTN, (BB * LL) / 128);       // (10, 32)
        tgemm_kernel<<<grid, 256>>>(gctx, Wo, Wo, Wo, bo,
                                    out, nullptr, nullptr, BB * LL, CC, CC);
    }
}

// round 11
// speedup vs baseline: 7.1330x; 1.5990x over previous
#include <cuda_runtime.h>
#include <cuda_fp16.h>
#include <cstdint>

// Problem constants
#define BB 4
#define LL 1024
#define CC 1280
#define HH 20
#define DH 64
#define BHH (BB*HH)        // 80
#define BANK 40
#define LPOOL 256          // (32/2)*(32/2)
#define LKV (LL + LPOOL)   // 1280
#define ALPHA_C 0.48f      // 0.8 * 0.6
#define QSCALE 0.125f      // 1/sqrt(64)
#define LOG2E 1.4426950408889634f

#define MROWS (BB*LL)      // 4096

// Scratch (device globals are allowed; cudaMalloc is not)
__device__ float  g_q[BB*LL*CC];
__device__ __half g_hsh[MROWS*CC];            // hs in fp16
__device__ __half g_wh[4][CC*CC];             // Wq,Wk,Wv,Wo in fp16
__device__ __half g_ctxh[MROWS*CC];           // attention output in fp16
__device__ __half g_kh[(size_t)BHH*LKV*DH];   // fused main+bank K, fp16 head-major
__device__ __half g_vh[(size_t)BHH*LKV*DH];

__device__ __forceinline__ float fp16_round(float x) {
    return __half2float(__float2half_rn(x));
}
__device__ __forceinline__ float ex2f(float x) {
    float y;
    asm("ex2.approx.ftz.f32 %0, %1;" : "=f"(y) : "f"(x));
    return y;
}
__device__ __forceinline__ void mma_f16(float* d, const unsigned* a, unsigned b0, unsigned b1) {
    asm volatile(
        "mma.sync.aligned.m16n8k16.row.col.f32.f16.f16.f32 "
        "{%0,%1,%2,%3}, {%4,%5,%6,%7}, {%8,%9}, {%0,%1,%2,%3};\n"
        : "+f"(d[0]), "+f"(d[1]), "+f"(d[2]), "+f"(d[3])
        : "r"(a[0]), "r"(a[1]), "r"(a[2]), "r"(a[3]),
          "r"(b0), "r"(b1));
}
__device__ __forceinline__ void cp16(uint32_t saddr, const void* gptr) {
    asm volatile("cp.async.cg.shared.global [%0], [%1], 16;\n"
                 :: "r"(saddr), "l"(gptr));
}
__device__ __forceinline__ void ldsm_x4(unsigned& r0, unsigned& r1, unsigned& r2,
                                        unsigned& r3, uint32_t a) {
    asm volatile("ldmatrix.sync.aligned.m8n8.x4.shared.b16 {%0,%1,%2,%3}, [%4];\n"
                 : "=r"(r0), "=r"(r1), "=r"(r2), "=r"(r3) : "r"(a));
}
__device__ __forceinline__ void ldsm_x4_t(unsigned& r0, unsigned& r1, unsigned& r2,
                                          unsigned& r3, uint32_t a) {
    asm volatile("ldmatrix.sync.aligned.m8n8.x4.trans.shared.b16 {%0,%1,%2,%3}, [%4];\n"
                 : "=r"(r0), "=r"(r1), "=r"(r2), "=r"(r3) : "r"(a));
}

// ---------------------------------------------------------------------------
// fp32 -> fp16 conversion: hs + 4 weight matrices, 8 elems/thread
// ---------------------------------------------------------------------------
#define HS_N8 (MROWS*CC/8)    // 655360
#define W_N8  (CC*CC/8)       // 204800

__global__ void cvt_kernel(const float* __restrict__ hs,
                           const float* __restrict__ Wq, const float* __restrict__ Wk,
                           const float* __restrict__ Wv, const float* __restrict__ Wo) {
    int idx = blockIdx.x * blockDim.x + threadIdx.x;
    const float* src;
    __half* dst;
    long off;
    if (idx < HS_N8) {
        src = hs; dst = g_hsh; off = (long)idx * 8;
    } else {
        int i2 = idx - HS_N8;
        int w = i2 / W_N8;
        if (w >= 4) return;
        off = (long)(i2 % W_N8) * 8;
        src = (w == 0) ? Wq : (w == 1) ? Wk : (w == 2) ? Wv : Wo;
        dst = g_wh[w];
    }
    float4 a = *(const float4*)(src + off);
    float4 b = *(const float4*)(src + off + 4);
    __half2 h0 = __floats2half2_rn(a.x, a.y);
    __half2 h1 = __floats2half2_rn(a.z, a.w);
    __half2 h2 = __floats2half2_rn(b.x, b.y);
    __half2 h3 = __floats2half2_rn(b.z, b.w);
    uint4 pack;
    pack.x = *(unsigned*)&h0; pack.y = *(unsigned*)&h1;
    pack.z = *(unsigned*)&h2; pack.w = *(unsigned*)&h3;
    *(uint4*)(dst + off) = pack;
}

// ---------------------------------------------------------------------------
// Bank KV: fp16 round -> 2x2 avg pool -> *ALPHA, write fp16 rows [1024..1279]
// of g_kh/g_vh for BOTH bh and bh+40 (bank repeats across batch).
// ---------------------------------------------------------------------------
__global__ void pool_kernel(const float* __restrict__ Kg,
                            const float* __restrict__ Vg) {
    int idx = blockIdx.x * blockDim.x + threadIdx.x;
    const int total = BANK * LPOOL * DH;
    if (idx >= total) return;
    int d  = idx % DH;
    int p  = (idx / DH) % LPOOL;
    int bh = idx / (DH * LPOOL);
    int ph = p >> 4;
    int pw = p & 15;
    int t0 = (2 * ph) * 32 + 2 * pw;
    long base = ((long)bh * LL + t0) * DH + d;

    float ks = fp16_round(Kg[base])         + fp16_round(Kg[base + DH])
             + fp16_round(Kg[base + 32*DH]) + fp16_round(Kg[base + 33*DH]);
    float vs = fp16_round(Vg[base])         + fp16_round(Vg[base + DH])
             + fp16_round(Vg[base + 32*DH]) + fp16_round(Vg[base + 33*DH]);
    __half kq = __float2half(ALPHA_C * (ks * 0.25f));
    __half vq = __float2half(ALPHA_C * (vs * 0.25f));
#pragma unroll
    for (int rep = 0; rep < 2; rep++) {
        long dst = ((long)(bh + rep * BANK) * LKV + LL + p) * DH + d;
        g_kh[dst] = kq;
        g_vh[dst] = vq;
    }
}

// ---------------------------------------------------------------------------
// fp16 tensor-core GEMM, 2-stage cp.async, fused over up to 3 weight mats.
// Block 128x128, BK=32, 8 warps (2m x 4n), warp tile 64x32.
// A [128][40] halves (80B stride), B [32][136] halves (272B stride):
// ldmatrix conflict-free. mat==0 -> fp32 C0(+bias); mat 1/2 -> fp16 head-major.
// ---------------------------------------------------------------------------
#define BKH 32
#define APADH 40
#define BPADH 136
#define NTN (CC/128)   // 10 n-tiles per matrix

__global__ __launch_bounds__(256)
void hgemm_kernel(const __half* __restrict__ A,
                  const __half* __restrict__ W0, const __half* __restrict__ W1,
                  const __half* __restrict__ W2, const float* __restrict__ bias,
                  float* __restrict__ C0, __half* __restrict__ HK,
                  __half* __restrict__ HV, int M, int N, int K) {
    __shared__ __half As[2][128 * APADH];
    __shared__ __half Bs[2][BKH * BPADH];

    int tid  = threadIdx.x;
    int lane = tid & 31;
    int wid  = tid >> 5;
    int wm   = wid >> 2;          // 0..1
    int wn   = wid & 3;           // 0..3
    int g    = lane >> 2;
    int tg   = lane & 3;
    int mm   = lane >> 3;         // 0..3 (ldmatrix sub-matrix)
    int r5   = lane & 7;

    int mat = blockIdx.x / NTN;
    int ntile = blockIdx.x % NTN;
    const __half* W = (mat == 0) ? W0 : (mat == 1) ? W1 : W2;

    int m0 = blockIdx.y * 128;
    int n0 = ntile * 128;

    // cp.async mappings (halves)
    int arow = tid >> 1;
    int acol = (tid & 1) * 16;    // two cp16 at acol, acol+8
    int brow = tid >> 3;
    int bcol = (tid & 7) * 16;

    uint32_t as_u = (uint32_t)__cvta_generic_to_shared(&As[0][0]);
    uint32_t bs_u = (uint32_t)__cvta_generic_to_shared(&Bs[0][0]);

    const __half* agp = A + (long)(m0 + arow) * K + acol;
    const __half* bgp = W + (long)brow * N + n0 + bcol;
    uint32_t asw = as_u + (uint32_t)(arow * APADH + acol) * 2u;
    uint32_t bsw = bs_u + (uint32_t)(brow * BPADH + bcol) * 2u;
    const uint32_t abuf = 128 * APADH * 2u;
    const uint32_t bbuf = BKH * BPADH * 2u;

    float acc[4][4][4];
#pragma unroll
    for (int i = 0; i < 4; i++)
#pragma unroll
        for (int j = 0; j < 4; j++)
#pragma unroll
            for (int r = 0; r < 4; r++) acc[i][j][r] = 0.f;

    const int NT = K / BKH;   // 40

    cp16(asw,      agp);
    cp16(asw + 16, agp + 8);
    cp16(bsw,      bgp);
    cp16(bsw + 16, bgp + 8);
    asm volatile("cp.async.commit_group;\n");

    for (int t = 0; t < NT; t++) {
        int cur = t & 1;
        if (t + 1 < NT) {
            int nxt = cur ^ 1;
            const __half* ag = agp + (t + 1) * BKH;
            const __half* bg = bgp + (long)(t + 1) * BKH * N;
            cp16(asw + nxt * abuf,      ag);
            cp16(asw + nxt * abuf + 16, ag + 8);
            cp16(bsw + nxt * bbuf,      bg);
            cp16(bsw + nxt * bbuf + 16, bg + 8);
            asm volatile("cp.async.commit_group;\n");
            asm volatile("cp.async.wait_group 1;\n");
        } else {
            asm volatile("cp.async.wait_group 0;\n");
        }
        __syncthreads();

        uint32_t aS = as_u + cur * abuf;
        uint32_t bS = bs_u + cur * bbuf;

#pragma unroll
        for (int tt = 0; tt < 2; tt++) {
            // A fragments: 4 x m16k16 via ldmatrix.x4
            unsigned af[4][4];
#pragma unroll
            for (int mf = 0; mf < 4; mf++) {
                int row = wm * 64 + mf * 16 + (mm & 1) * 8 + r5;
                uint32_t a = aS + (uint32_t)((row * APADH + tt * 16 + (mm >> 1) * 8) * 2);
                ldsm_x4(af[mf][0], af[mf][1], af[mf][2], af[mf][3], a);
            }
            // B fragments + mma: 2 x (k16 n16) via ldmatrix.x4.trans
#pragma unroll
            for (int j2 = 0; j2 < 2; j2++) {
                unsigned b0, b1, b2, b3;
                int krow = tt * 16 + (mm & 1) * 8 + r5;
                int col  = wn * 32 + j2 * 16 + (mm >> 1) * 8;
                uint32_t a = bS + (uint32_t)((krow * BPADH + col) * 2);
                ldsm_x4_t(b0, b1, b2, b3, a);
#pragma unroll
                for (int mf = 0; mf < 4; mf++) {
                    mma_f16(acc[mf][2 * j2],     af[mf], b0, b1);
                    mma_f16(acc[mf][2 * j2 + 1], af[mf], b2, b3);
                }
            }
        }
        __syncthreads();
    }

    // Epilogue
    if (mat == 0) {
#pragma unroll
        for (int mf = 0; mf < 4; mf++) {
            long r0 = m0 + wm * 64 + mf * 16 + g;
#pragma unroll
            for (int nf = 0; nf < 4; nf++) {
                int c = n0 + wn * 32 + nf * 8 + tg * 2;
                float b0 = bias ? bias[c] : 0.f;
                float b1 = bias ? bias[c + 1] : 0.f;
                float2 v0 = {acc[mf][nf][0] + b0, acc[mf][nf][1] + b1};
                float2 v1 = {acc[mf][nf][2] + b0, acc[mf][nf][3] + b1};
                *(float2*)(C0 + r0 * N + c)       = v0;
                *(float2*)(C0 + (r0 + 8) * N + c) = v1;
            }
        }
    } else {
        __half* H = (mat == 1) ? HK : HV;
#pragma unroll
        for (int mf = 0; mf < 4; mf++) {
            int r0 = m0 + wm * 64 + mf * 16 + g;
#pragma unroll
            for (int nf = 0; nf < 4; nf++) {
                int c = n0 + wn * 32 + nf * 8 + tg * 2;
                int h = c >> 6, d = c & 63;
#pragma unroll
                for (int rr = 0; rr < 2; rr++) {
                    int row = r0 + rr * 8;
                    int b = row >> 10, l = row & 1023;
                    long dst = ((long)(b * HH + h) * LKV + l) * DH + d;
                    __half2 hv = __floats2half2_rn(acc[mf][nf][rr * 2],
                                                   acc[mf][nf][rr * 2 + 1]);
                    *(__half2*)(&H[dst]) = hv;
                }
            }
        }
    }
}

// ---------------------------------------------------------------------------
// Flash attention, fp16 tensor cores. Block = (head, 128 q rows), 8 warps,
// each warp owns 16 q rows. KV tiles of 64, double-buffered cp.async.
// Smem: K,V [64][72] fp16 x2 buffers = 36864 B. ctx written in fp16.
// ---------------------------------------------------------------------------
#define KPAD 72
#define KVT  (64 * KPAD)

__global__ __launch_bounds__(256)
void flash_tc_kernel(const float* __restrict__ q, const __half* __restrict__ kh,
                     const __half* __restrict__ vh, __half* __restrict__ ctxh) {
    __shared__ __half sKV[2][2][KVT];   // [buf][0=K,1=V]

    int tid  = threadIdx.x;
    int lane = tid & 31;
    int w    = tid >> 5;
    int g    = lane >> 2;
    int tg   = lane & 3;
    int bh = blockIdx.y;
    int bb = bh / HH;
    int hh = bh % HH;
    int q0 = blockIdx.x * 128;
    int qrow = q0 + w * 16 + g;

    // Q fragments from gmem, scaled by QSCALE*log2e (log2-domain softmax)
    const float sca = QSCALE * LOG2E;
    unsigned qa[4][4];
    {
        const float* qp = q + ((long)bb * LL + qrow) * CC + hh * DH;
#pragma unroll
        for (int t = 0; t < 4; t++) {
            float2 x0 = *(const float2*)(qp + 16 * t + 2 * tg);
            float2 x1 = *(const float2*)(qp + 8 * CC + 16 * t + 2 * tg);
            float2 x2 = *(const float2*)(qp + 16 * t + 8 + 2 * tg);
            float2 x3 = *(const float2*)(qp + 8 * CC + 16 * t + 8 + 2 * tg);
            __half2 h0 = __floats2half2_rn(x0.x * sca, x0.y * sca);
            __half2 h1 = __floats2half2_rn(x1.x * sca, x1.y * sca);
            __half2 h2 = __floats2half2_rn(x2.x * sca, x2.y * sca);
            __half2 h3 = __floats2half2_rn(x3.x * sca, x3.y * sca);
            qa[t][0] = *(unsigned*)&h0;
            qa[t][1] = *(unsigned*)&h1;
            qa[t][2] = *(unsigned*)&h2;
            qa[t][3] = *(unsigned*)&h3;
        }
    }

    // cp.async load mapping: 256 threads, tensor = tid>>7, 2 threads/row
    int tsel = tid >> 7;
    int idxl = tid & 127;
    int lrow = idxl >> 1;
    int lhf  = idxl & 1;
    const __half* gsrc0 = (tsel ? vh : kh) + ((long)bh * LKV) * DH
                        + lrow * DH + lhf * 32;
    uint32_t sdst0 = (uint32_t)__cvta_generic_to_shared(&sKV[0][tsel][0])
                   + (uint32_t)(lrow * KPAD + lhf * 32) * 2u;
    const uint32_t bufstep = 2u * KVT * 2u;

    float m0v = -1e30f, m1v = -1e30f, l0 = 0.f, l1 = 0.f;
    float O[8][4];
#pragma unroll
    for (int j = 0; j < 8; j++)
#pragma unroll
        for (int r = 0; r < 4; r++) O[j][r] = 0.f;

    const int NT = LKV / 64;   // 20

    {
        const __half* s = gsrc0;
#pragma unroll
        for (int i = 0; i < 4; i++) cp16(sdst0 + i * 16, s + i * 8);
        asm volatile("cp.async.commit_group;\n");
    }

    for (int t = 0; t < NT; t++) {
        int cur = t & 1;
        if (t + 1 < NT) {
            const __half* s = gsrc0 + (long)(t + 1) * 64 * DH;
            uint32_t dd = sdst0 + (cur ^ 1) * bufstep;
#pragma unroll
            for (int i = 0; i < 4; i++) cp16(dd + i * 16, s + i * 8);
            asm volatile("cp.async.commit_group;\n");
            asm volatile("cp.async.wait_group 1;\n");
        } else {
            asm volatile("cp.async.wait_group 0;\n");
        }
        __syncthreads();

        uint32_t kbase = (uint32_t)__cvta_generic_to_shared(&sKV[cur][0][0]);
        uint32_t vbase = (uint32_t)__cvta_generic_to_shared(&sKV[cur][1][0]);
        int mm = lane >> 3;
        int r5 = lane & 7;

        // S = Q K^T (log2 domain)
        float sacc[8][4];
#pragma unroll
        for (int j = 0; j < 8; j++)
#pragma unroll
            for (int r = 0; r < 4; r++) sacc[j][r] = 0.f;

#pragma unroll
        for (int tt = 0; tt < 4; tt++) {
#pragma unroll
            for (int j2 = 0; j2 < 4; j2++) {
                unsigned b0, b1, b2, b3;
                uint32_t a = kbase +
                    (uint32_t)(((j2 * 16 + (mm >> 1) * 8 + r5) * KPAD
                                + tt * 16 + (mm & 1) * 8) * 2);
                ldsm_x4(b0, b1, b2, b3, a);
                mma_f16(sacc[2 * j2],     qa[tt], b0, b1);
                mma_f16(sacc[2 * j2 + 1], qa[tt], b2, b3);
            }
        }

        // Online softmax
        float mx0 = -1e30f, mx1 = -1e30f;
#pragma unroll
        for (int j = 0; j < 8; j++) {
            mx0 = fmaxf(mx0, fmaxf(sacc[j][0], sacc[j][1]));
            mx1 = fmaxf(mx1, fmaxf(sacc[j][2], sacc[j][3]));
        }
        mx0 = fmaxf(mx0, __shfl_xor_sync(0xffffffffu, mx0, 1));
        mx0 = fmaxf(mx0, __shfl_xor_sync(0xffffffffu, mx0, 2));
        mx1 = fmaxf(mx1, __shfl_xor_sync(0xffffffffu, mx1, 1));
        mx1 = fmaxf(mx1, __shfl_xor_sync(0xffffffffu, mx1, 2));

        float mn0 = fmaxf(m0v, mx0);
        float mn1 = fmaxf(m1v, mx1);
        float sc0 = ex2f(m0v - mn0);
        float sc1 = ex2f(m1v - mn1);
        m0v = mn0; m1v = mn1;

        float pex[8][4];
        float su0 = 0.f, su1 = 0.f;
#pragma unroll
        for (int j = 0; j < 8; j++) {
            pex[j][0] = ex2f(sacc[j][0] - mn0);
            pex[j][1] = ex2f(sacc[j][1] - mn0);
            pex[j][2] = ex2f(sacc[j][2] - mn1);
            pex[j][3] = ex2f(sacc[j][3] - mn1);
            su0 += pex[j][0] + pex[j][1];
            su1 += pex[j][2] + pex[j][3];
        }
        su0 += __shfl_xor_sync(0xffffffffu, su0, 1);
        su0 += __shfl_xor_sync(0xffffffffu, su0, 2);
        su1 += __shfl_xor_sync(0xffffffffu, su1, 1);
        su1 += __shfl_xor_sync(0xffffffffu, su1, 2);
        l0 = l0 * sc0 + su0;
        l1 = l1 * sc1 + su1;

#pragma unroll
        for (int j = 0; j < 8; j++) {
            O[j][0] *= sc0; O[j][1] *= sc0;
            O[j][2] *= sc1; O[j][3] *= sc1;
        }

        // Pack P fragments directly from accumulators (C layout == A layout)
        unsigned paf[4][4];
#pragma unroll
        for (int tt = 0; tt < 4; tt++) {
            __half2 a0 = __floats2half2_rn(pex[2*tt][0],   pex[2*tt][1]);
            __half2 a1 = __floats2half2_rn(pex[2*tt][2],   pex[2*tt][3]);
            __half2 a2 = __floats2half2_rn(pex[2*tt+1][0], pex[2*tt+1][1]);
            __half2 a3 = __floats2half2_rn(pex[2*tt+1][2], pex[2*tt+1][3]);
            paf[tt][0] = *(unsigned*)&a0;
            paf[tt][1] = *(unsigned*)&a1;
            paf[tt][2] = *(unsigned*)&a2;
            paf[tt][3] = *(unsigned*)&a3;
        }

        // O += P V  (V^T fragments via ldmatrix.trans)
#pragma unroll
        for (int tt = 0; tt < 4; tt++) {
#pragma unroll
            for (int j2 = 0; j2 < 4; j2++) {
                unsigned b0, b1, b2, b3;
                uint32_t a = vbase +
                    (uint32_t)(((tt * 16 + (mm & 1) * 8 + r5) * KPAD
                                + j2 * 16 + (mm >> 1) * 8) * 2);
                ldsm_x4_t(b0, b1, b2, b3, a);
                mma_f16(O[2 * j2],     paf[tt], b0, b1);
                mma_f16(O[2 * j2 + 1], paf[tt], b2, b3);
            }
        }
        __syncthreads();
    }

    // Normalize + write ctx (fp16) in [B, L, H*Dh]
    float inv0 = 1.f / l0;
    float inv1 = 1.f / l1;
    __half* cp0 = ctxh + ((long)bb * LL + qrow) * CC + hh * DH;
#pragma unroll
    for (int j = 0; j < 8; j++) {
        __half2 v0 = __floats2half2_rn(O[j][0] * inv0, O[j][1] * inv0);
        __half2 v1 = __floats2half2_rn(O[j][2] * inv1, O[j][3] * inv1);
        *(__half2*)(cp0 + 8 * j + 2 * tg)          = v0;
        *(__half2*)(cp0 + 8 * CC + 8 * j + 2 * tg) = v1;
    }
}

// ---------------------------------------------------------------------------
extern "C" void kernel_launch(void* const* d_in, const int* in_sizes, int n_in,
                              void* d_out, int out_size) {
    const float* hs  = (const float*)d_in[0];
    const float* Wq  = (const float*)d_in[1];
    const float* Wk  = (const float*)d_in[2];
    const float* Wv  = (const float*)d_in[3];
    const float* Wo  = (const float*)d_in[4];
    const float* bo  = (const float*)d_in[5];
    const float* Kbg = (const float*)d_in[6];
    const float* Vbg = (const float*)d_in[7];
    float* out = (float*)d_out;

    float *gq;
    __half *ghsh, *gwh, *gctxh, *gkh, *gvh;
    cudaGetSymbolAddress((void**)&gq,    g_q);
    cudaGetSymbolAddress((void**)&ghsh,  g_hsh);
    cudaGetSymbolAddress((void**)&gwh,   g_wh);
    cudaGetSymbolAddress((void**)&gctxh, g_ctxh);
    cudaGetSymbolAddress((void**)&gkh,   g_kh);
    cudaGetSymbolAddress((void**)&gvh,   g_vh);

    const __half* whQ = gwh;
    const __half* whK = gwh + (size_t)CC * CC;
    const __half* whV = gwh + 2 * (size_t)CC * CC;
    const __half* whO = gwh + 3 * (size_t)CC * CC;

    // 0. Convert hs + weights to fp16
    {
        int total = HS_N8 + 4 * W_N8;
        cvt_kernel<<<(total + 255) / 256, 256>>>(hs, Wq, Wk, Wv, Wo);
    }

    // 1. Bank KV pool -> fp16 rows [1024..1280) of g_kh/g_vh
    {
        int total = BANK * LPOOL * DH;
        pool_kernel<<<(total + 255) / 256, 256>>>(Kbg, Vbg);
    }

    // 2. Fused QKV projections (fp16 TC); K/V epilogue writes head-major fp16
    {
        dim3 grid(3 * NTN, MROWS / 128);   // (30, 32)
        hgemm_kernel<<<grid, 256>>>(ghsh, whQ, whK, whV, nullptr,
                                    gq, gkh, gvh, MROWS, CC, CC);
    }

    // 3. Flash attention on fp16 tensor cores -> fp16 ctx
    {
        dim3 grid(LL / 128, BHH);   // (8, 80)
        flash_tc_kernel<<<grid, 256>>>(gq, gkh, gvh, gctxh);
    }

    // 4. Output projection + bias (fp16 TC)
    {
        dim3 grid(NTN, MROWS / 128);       // (10, 32)
        hgemm_kernel<<<grid, 256>>>(gctxh, whO, whO, whO, bo,
                                    out, nullptr, nullptr, MROWS, CC, CC);
    }
}